// round 9
// baseline (speedup 1.0000x reference)
#include <cuda_runtime.h>
#include <cuda_bf16.h>

#define BATCH   32768
#define HID     128
#define INF     784
#define NCLS    10
#define TSTEPS  20

#define DECAYF  0.25f
#define THRESHF 1.0f
#define EPSM    2e-4f

#define KCHUNKS (INF / 16)      // 49
#define FIXCAP  (1 << 21)

// Scratch (device globals)
__device__ float    g_c2[(size_t)TSTEPS * BATCH * NCLS];
__device__ unsigned g_fix_list[FIXCAP];
__device__ unsigned g_fix_cnt;
__device__ __align__(16) unsigned short g_w1a[HID * INF];   // bf16 hi plane
__device__ __align__(16) unsigned short g_w1b[HID * INF];   // bf16 lo plane

// ---------------------------------------------------------------------------
__device__ __forceinline__ void split2(float v, unsigned short& h0, unsigned short& h1)
{
    __nv_bfloat16 b0 = __float2bfloat16_rn(v);
    float r = v - __bfloat162float(b0);
    __nv_bfloat16 b1 = __float2bfloat16_rn(r);
    h0 = __bfloat16_as_ushort(b0);
    h1 = __bfloat16_as_ushort(b1);
}

__device__ __forceinline__ void mma_bf16(float* d, const unsigned* a, const unsigned* b)
{
    asm volatile(
        "mma.sync.aligned.m16n8k16.row.col.f32.bf16.bf16.f32 "
        "{%0,%1,%2,%3}, {%4,%5,%6,%7}, {%8,%9}, {%0,%1,%2,%3};"
        : "+f"(d[0]), "+f"(d[1]), "+f"(d[2]), "+f"(d[3])
        : "r"(a[0]), "r"(a[1]), "r"(a[2]), "r"(a[3]), "r"(b[0]), "r"(b[1]));
}

__global__ void k0_init(const float* __restrict__ W1)
{
    if (blockIdx.x == 0 && threadIdx.x == 0) g_fix_cnt = 0;
    int i = blockIdx.x * blockDim.x + threadIdx.x;
    if (i < HID * INF) {
        unsigned short h0, h1;
        split2(W1[i], h0, h1);
        g_w1a[i] = h0;
        g_w1b[i] = h1;
    }
}

// ---------------------------------------------------------------------------
// K1 hybrid: per CTA, 64 batch rows.
//   warps 0-3 (tid 0..127):  rows m0..m0+31  via bf16x2-split MMA (3 products)
//                            + LIF + margin tracking (fixup list).
//   warps 4-7 (tid 128..255): rows m0+32..m0+63 via EXACT fp32 FFMA GEMM
//                            (R1 recipe, ascending-k) + LIF. No fixup needed.
// Both groups iterate the same 49 k-chunks; CTA barriers align.
// ---------------------------------------------------------------------------
#define ASTRIDE 24    // tensor A smem stride (ushorts)
#define BSTRIDE 16    // tensor B smem stride (ushorts)

// static smem layout (bytes):
//   [0,      6144)  tensor A: ushort[2buf][2pl][32*ASTRIDE]
//   [6144,  22528)  tensor B: ushort[2buf][2pl][128*BSTRIDE]
//   [22528, 26624)  fp32 A:   float[2buf][16][32]
//   [26624, 43008)  fp32 B:   float[2buf][16][128]
#define SM_TA  0
#define SM_TB  6144
#define SM_FA  22528
#define SM_FB  26624
#define SM_TOT 43008

__global__ __launch_bounds__(256) void k1_hybrid(
    const float* __restrict__ x, const float* __restrict__ W1,
    const float* __restrict__ b1, float* __restrict__ out_spk)
{
    __shared__ __align__(16) char SM[SM_TOT];

    const int tid = threadIdx.x;
    const int m0  = blockIdx.x * 64;
    const bool tpath = (tid < 128);

    // ---------------- tensor-path ids ----------------
    const int lane = tid & 31;
    const int wid  = tid >> 5;          // 0..3 tensor, 4..7 fp32
    const int g    = lane >> 2;
    const int tg   = lane & 3;
    const int wn   = wid & 3;           // tensor: n-quarter
    const int sm_r = tid >> 2;          // tensor A stage row 0..31
    const int skq  = (tid & 3) * 4;     // tensor A stage k 0,4,8,12
    const int bn   = tid;               // tensor B stage row 0..127

    // ---------------- fp32-path ids ----------------
    const int ltid = tid - 128;         // 0..127
    const int ftx  = ltid & 15;         // n-group (8 cols)
    const int fty  = ltid >> 4;         // m-group (4 rows), 0..7
    const int fm0  = m0 + 32;

    // accumulators (each path uses its own)
    float tacc[2][4][4];                // tensor: [mt][nt][r]
    float facc[4][8];                   // fp32:   [row][col]
    if (tpath) {
        #pragma unroll
        for (int mt = 0; mt < 2; mt++)
            #pragma unroll
            for (int nt = 0; nt < 4; nt++)
                #pragma unroll
                for (int r = 0; r < 4; r++) tacc[mt][nt][r] = 0.0f;
    } else {
        #pragma unroll
        for (int i = 0; i < 4; i++)
            #pragma unroll
            for (int j = 0; j < 8; j++) facc[i][j] = 0.0f;
    }

    unsigned short* TA = (unsigned short*)(SM + SM_TA);
    unsigned short* TB = (unsigned short*)(SM + SM_TB);
    float*          FA = (float*)(SM + SM_FA);
    float*          FB = (float*)(SM + SM_FB);

    // ---- stage chunk 0 into buf 0 ----
    if (tpath) {
        float4 ax = *reinterpret_cast<const float4*>(&x[(size_t)(m0 + sm_r) * INF + skq]);
        float av[4] = {ax.x, ax.y, ax.z, ax.w};
        unsigned short p0[4], p1[4];
        #pragma unroll
        for (int i = 0; i < 4; i++) split2(av[i], p0[i], p1[i]);
        *reinterpret_cast<uint2*>(&TA[(0 * 2 + 0) * (32 * ASTRIDE) + sm_r * ASTRIDE + skq]) = *reinterpret_cast<uint2*>(p0);
        *reinterpret_cast<uint2*>(&TA[(0 * 2 + 1) * (32 * ASTRIDE) + sm_r * ASTRIDE + skq]) = *reinterpret_cast<uint2*>(p1);
        uint4 a0 = *reinterpret_cast<const uint4*>(&g_w1a[(size_t)bn * INF + 0]);
        uint4 a1 = *reinterpret_cast<const uint4*>(&g_w1a[(size_t)bn * INF + 8]);
        uint4 c0 = *reinterpret_cast<const uint4*>(&g_w1b[(size_t)bn * INF + 0]);
        uint4 c1 = *reinterpret_cast<const uint4*>(&g_w1b[(size_t)bn * INF + 8]);
        *reinterpret_cast<uint4*>(&TB[(0 * 2 + 0) * (128 * BSTRIDE) + bn * BSTRIDE + 0]) = a0;
        *reinterpret_cast<uint4*>(&TB[(0 * 2 + 0) * (128 * BSTRIDE) + bn * BSTRIDE + 8]) = a1;
        *reinterpret_cast<uint4*>(&TB[(0 * 2 + 1) * (128 * BSTRIDE) + bn * BSTRIDE + 0]) = c0;
        *reinterpret_cast<uint4*>(&TB[(0 * 2 + 1) * (128 * BSTRIDE) + bn * BSTRIDE + 8]) = c1;
    } else {
        // fp32 A: 32 rows x 16 k = 128 float4, 1 per thread (transposed store)
        {
            int r = ltid >> 2, kq = (ltid & 3) * 4;
            float4 v = *reinterpret_cast<const float4*>(&x[(size_t)(fm0 + r) * INF + kq]);
            FA[(0 * 16 + kq + 0) * 32 + r] = v.x;
            FA[(0 * 16 + kq + 1) * 32 + r] = v.y;
            FA[(0 * 16 + kq + 2) * 32 + r] = v.z;
            FA[(0 * 16 + kq + 3) * 32 + r] = v.w;
        }
        // fp32 B: 128 rows x 16 k = 512 float4, 4 per thread
        #pragma unroll
        for (int it = 0; it < 4; it++) {
            int f = ltid + it * 128;
            int n = f >> 2, kq = (f & 3) * 4;
            float4 v = *reinterpret_cast<const float4*>(&W1[(size_t)n * INF + kq]);
            FB[(0 * 16 + kq + 0) * 128 + n] = v.x;
            FB[(0 * 16 + kq + 1) * 128 + n] = v.y;
            FB[(0 * 16 + kq + 2) * 128 + n] = v.z;
            FB[(0 * 16 + kq + 3) * 128 + n] = v.w;
        }
    }
    __syncthreads();

    int buf = 0;
    for (int kc = 0; kc < KCHUNKS; kc++) {
        const bool more = (kc + 1 < KCHUNKS);
        // ---- prefetch next chunk into registers ----
        float4 pax, pfa, pfb0, pfb1, pfb2, pfb3;
        uint4 pba0, pba1, pbb0, pbb1;
        if (more) {
            int k0 = (kc + 1) * 16;
            if (tpath) {
                pax  = *reinterpret_cast<const float4*>(&x[(size_t)(m0 + sm_r) * INF + k0 + skq]);
                pba0 = *reinterpret_cast<const uint4*>(&g_w1a[(size_t)bn * INF + k0 + 0]);
                pba1 = *reinterpret_cast<const uint4*>(&g_w1a[(size_t)bn * INF + k0 + 8]);
                pbb0 = *reinterpret_cast<const uint4*>(&g_w1b[(size_t)bn * INF + k0 + 0]);
                pbb1 = *reinterpret_cast<const uint4*>(&g_w1b[(size_t)bn * INF + k0 + 8]);
            } else {
                int r = ltid >> 2, kq = (ltid & 3) * 4;
                pfa = *reinterpret_cast<const float4*>(&x[(size_t)(fm0 + r) * INF + k0 + kq]);
                int n0 = (ltid + 0 * 128) >> 2, kq0 = ((ltid + 0 * 128) & 3) * 4;
                int n1 = (ltid + 1 * 128) >> 2, kq1 = ((ltid + 1 * 128) & 3) * 4;
                int n2 = (ltid + 2 * 128) >> 2, kq2 = ((ltid + 2 * 128) & 3) * 4;
                int n3 = (ltid + 3 * 128) >> 2, kq3 = ((ltid + 3 * 128) & 3) * 4;
                pfb0 = *reinterpret_cast<const float4*>(&W1[(size_t)n0 * INF + k0 + kq0]);
                pfb1 = *reinterpret_cast<const float4*>(&W1[(size_t)n1 * INF + k0 + kq1]);
                pfb2 = *reinterpret_cast<const float4*>(&W1[(size_t)n2 * INF + k0 + kq2]);
                pfb3 = *reinterpret_cast<const float4*>(&W1[(size_t)n3 * INF + k0 + kq3]);
            }
        }

        // ---- compute chunk kc ----
        if (tpath) {
            unsigned aF[2][2][4];
            #pragma unroll
            for (int s = 0; s < 2; s++)
                #pragma unroll
                for (int mt = 0; mt < 2; mt++) {
                    const unsigned short* ap = &TA[(buf * 2 + s) * (32 * ASTRIDE) + (mt * 16) * ASTRIDE];
                    aF[s][mt][0] = *reinterpret_cast<const unsigned*>(&ap[(g)     * ASTRIDE + tg * 2]);
                    aF[s][mt][1] = *reinterpret_cast<const unsigned*>(&ap[(g + 8) * ASTRIDE + tg * 2]);
                    aF[s][mt][2] = *reinterpret_cast<const unsigned*>(&ap[(g)     * ASTRIDE + tg * 2 + 8]);
                    aF[s][mt][3] = *reinterpret_cast<const unsigned*>(&ap[(g + 8) * ASTRIDE + tg * 2 + 8]);
                }
            unsigned bF[2][4][2];
            #pragma unroll
            for (int s = 0; s < 2; s++)
                #pragma unroll
                for (int nt = 0; nt < 4; nt++) {
                    const unsigned short* bp = &TB[(buf * 2 + s) * (128 * BSTRIDE) + (wn * 32 + nt * 8 + g) * BSTRIDE];
                    bF[s][nt][0] = *reinterpret_cast<const unsigned*>(&bp[tg * 2]);
                    bF[s][nt][1] = *reinterpret_cast<const unsigned*>(&bp[tg * 2 + 8]);
                }
            #pragma unroll
            for (int p = 0; p < 3; p++) {
                const int PI[3] = {0, 0, 1};
                const int PJ[3] = {0, 1, 0};
                int i = PI[p], j = PJ[p];
                #pragma unroll
                for (int mt = 0; mt < 2; mt++)
                    #pragma unroll
                    for (int nt = 0; nt < 4; nt++)
                        mma_bf16(tacc[mt][nt], aF[i][mt], bF[j][nt]);
            }
        } else {
            const float* fa = &FA[buf * 16 * 32];
            const float* fb = &FB[buf * 16 * 128];
            #pragma unroll
            for (int k = 0; k < 16; k++) {
                float4 a4 = *reinterpret_cast<const float4*>(&fa[k * 32 + fty * 4]);
                float4 b0 = *reinterpret_cast<const float4*>(&fb[k * 128 + ftx * 8]);
                float4 b1v = *reinterpret_cast<const float4*>(&fb[k * 128 + ftx * 8 + 4]);
                float a[4] = {a4.x, a4.y, a4.z, a4.w};
                float b[8] = {b0.x, b0.y, b0.z, b0.w, b1v.x, b1v.y, b1v.z, b1v.w};
                #pragma unroll
                for (int i = 0; i < 4; i++)
                    #pragma unroll
                    for (int j = 0; j < 8; j++)
                        facc[i][j] = fmaf(a[i], b[j], facc[i][j]);
            }
        }

        // ---- store prefetched chunk into other buffer ----
        if (more) {
            int ob = buf ^ 1;
            if (tpath) {
                float av[4] = {pax.x, pax.y, pax.z, pax.w};
                unsigned short p0[4], p1[4];
                #pragma unroll
                for (int i = 0; i < 4; i++) split2(av[i], p0[i], p1[i]);
                *reinterpret_cast<uint2*>(&TA[(ob * 2 + 0) * (32 * ASTRIDE) + sm_r * ASTRIDE + skq]) = *reinterpret_cast<uint2*>(p0);
                *reinterpret_cast<uint2*>(&TA[(ob * 2 + 1) * (32 * ASTRIDE) + sm_r * ASTRIDE + skq]) = *reinterpret_cast<uint2*>(p1);
                *reinterpret_cast<uint4*>(&TB[(ob * 2 + 0) * (128 * BSTRIDE) + bn * BSTRIDE + 0]) = pba0;
                *reinterpret_cast<uint4*>(&TB[(ob * 2 + 0) * (128 * BSTRIDE) + bn * BSTRIDE + 8]) = pba1;
                *reinterpret_cast<uint4*>(&TB[(ob * 2 + 1) * (128 * BSTRIDE) + bn * BSTRIDE + 0]) = pbb0;
                *reinterpret_cast<uint4*>(&TB[(ob * 2 + 1) * (128 * BSTRIDE) + bn * BSTRIDE + 8]) = pbb1;
            } else {
                int r = ltid >> 2, kq = (ltid & 3) * 4;
                FA[(ob * 16 + kq + 0) * 32 + r] = pfa.x;
                FA[(ob * 16 + kq + 1) * 32 + r] = pfa.y;
                FA[(ob * 16 + kq + 2) * 32 + r] = pfa.z;
                FA[(ob * 16 + kq + 3) * 32 + r] = pfa.w;
                float4 pv[4] = {pfb0, pfb1, pfb2, pfb3};
                #pragma unroll
                for (int it = 0; it < 4; it++) {
                    int f = ltid + it * 128;
                    int n = f >> 2, kq2 = (f & 3) * 4;
                    FB[(ob * 16 + kq2 + 0) * 128 + n] = pv[it].x;
                    FB[(ob * 16 + kq2 + 1) * 128 + n] = pv[it].y;
                    FB[(ob * 16 + kq2 + 2) * 128 + n] = pv[it].z;
                    FB[(ob * 16 + kq2 + 3) * 128 + n] = pv[it].w;
                }
            }
        }
        __syncthreads();
        buf ^= 1;
    }

    // ================= epilogues (no barriers below) =================
    if (tpath) {
        float cur[2][4][4];
        #pragma unroll
        for (int nt = 0; nt < 4; nt++) {
            float2 bv = *reinterpret_cast<const float2*>(&b1[wn * 32 + nt * 8 + tg * 2]);
            #pragma unroll
            for (int mt = 0; mt < 2; mt++) {
                cur[mt][nt][0] = tacc[mt][nt][0] + bv.x;
                cur[mt][nt][1] = tacc[mt][nt][1] + bv.y;
                cur[mt][nt][2] = tacc[mt][nt][2] + bv.x;
                cur[mt][nt][3] = tacc[mt][nt][3] + bv.y;
            }
        }
        float mem[2][4][4];
        unsigned badm[2][4];
        #pragma unroll
        for (int mt = 0; mt < 2; mt++)
            #pragma unroll
            for (int nt = 0; nt < 4; nt++) {
                badm[mt][nt] = 0u;
                #pragma unroll
                for (int r = 0; r < 4; r++) mem[mt][nt][r] = 0.0f;
            }

        for (int t = 0; t < TSTEPS; t++) {
            float* pt = out_spk + (size_t)t * ((size_t)BATCH * HID);
            #pragma unroll
            for (int mt = 0; mt < 2; mt++) {
                int r0 = m0 + mt * 16 + g;
                #pragma unroll
                for (int nt = 0; nt < 4; nt++) {
                    int n = wn * 32 + nt * 8 + tg * 2;
                    float s[4];
                    #pragma unroll
                    for (int r = 0; r < 4; r++) {
                        float m = fmaf(mem[mt][nt][r], DECAYF, cur[mt][nt][r]);
                        if (fabsf(m - THRESHF) < EPSM) badm[mt][nt] |= (1u << r);
                        s[r] = (m > THRESHF) ? 1.0f : 0.0f;
                        mem[mt][nt][r] = (s[r] != 0.0f) ? 0.0f : m;
                    }
                    float2 v0 = {s[0], s[1]};
                    float2 v1 = {s[2], s[3]};
                    *reinterpret_cast<float2*>(&pt[(size_t)r0 * HID + n])       = v0;
                    *reinterpret_cast<float2*>(&pt[(size_t)(r0 + 8) * HID + n]) = v1;
                }
            }
        }
        #pragma unroll
        for (int mt = 0; mt < 2; mt++)
            #pragma unroll
            for (int nt = 0; nt < 4; nt++)
                if (badm[mt][nt]) {
                    #pragma unroll
                    for (int r = 0; r < 4; r++)
                        if (badm[mt][nt] & (1u << r)) {
                            int row = m0 + mt * 16 + g + ((r >> 1) ? 8 : 0);
                            int col = wn * 32 + nt * 8 + tg * 2 + (r & 1);
                            unsigned pos = atomicAdd(&g_fix_cnt, 1u);
                            if (pos < FIXCAP)
                                g_fix_list[pos] = (unsigned)(row * HID + col);
                        }
                }
    } else {
        // fp32 path: exact. cur = acc + b1, LIF, stores.
        float bb[8];
        #pragma unroll
        for (int j = 0; j < 8; j++) bb[j] = __ldg(&b1[ftx * 8 + j]);
        float cur[4][8], mem[4][8];
        #pragma unroll
        for (int i = 0; i < 4; i++)
            #pragma unroll
            for (int j = 0; j < 8; j++) {
                cur[i][j] = facc[i][j] + bb[j];
                mem[i][j] = 0.0f;
            }
        for (int t = 0; t < TSTEPS; t++) {
            float* pt = out_spk + (size_t)t * ((size_t)BATCH * HID);
            #pragma unroll
            for (int i = 0; i < 4; i++) {
                float s[8];
                #pragma unroll
                for (int j = 0; j < 8; j++) {
                    mem[i][j] = fmaf(mem[i][j], DECAYF, cur[i][j]);
                    s[j] = (mem[i][j] > THRESHF) ? 1.0f : 0.0f;
                    mem[i][j] = (s[j] != 0.0f) ? 0.0f : mem[i][j];
                }
                float4 v0 = {s[0], s[1], s[2], s[3]};
                float4 v1 = {s[4], s[5], s[6], s[7]};
                float* pr = &pt[(size_t)(fm0 + fty * 4 + i) * HID + ftx * 8];
                *reinterpret_cast<float4*>(pr)     = v0;
                *reinterpret_cast<float4*>(pr + 4) = v1;
            }
        }
    }
}

// ---------------------------------------------------------------------------
// K1b fixup: exact sequential-k fp32 recompute of spikes (bitwise R1 recipe).
// ---------------------------------------------------------------------------
__global__ __launch_bounds__(128) void k1_fixup(
    const float* __restrict__ x, const float* __restrict__ W1,
    const float* __restrict__ b1, float* __restrict__ out_spk)
{
    const unsigned cnt = min(*(volatile unsigned*)&g_fix_cnt, (unsigned)FIXCAP);
    const int stride = gridDim.x * blockDim.x;

    for (unsigned i = blockIdx.x * blockDim.x + threadIdx.x; i < cnt; i += stride) {
        unsigned idx = g_fix_list[i];
        int b = idx >> 7;
        int j = idx & (HID - 1);

        const float* xr = x  + (size_t)b * INF;
        const float* wr = W1 + (size_t)j * INF;
        float a = 0.0f;
        for (int k = 0; k < INF; k++)
            a = fmaf(__ldg(&xr[k]), __ldg(&wr[k]), a);
        float curv = a + __ldg(&b1[j]);

        float m = 0.0f;
        for (int t = 0; t < TSTEPS; t++) {
            m = fmaf(m, DECAYF, curv);
            float s = (m > THRESHF) ? 1.0f : 0.0f;
            out_spk[(size_t)t * ((size_t)BATCH * HID) + idx] = s;
            m = (s != 0.0f) ? 0.0f : m;
        }
    }
}

// ---------------------------------------------------------------------------
// K3: c2 = spk @ W2^T (verbatim R5 — proven, bitwise == R1 chain).
// ---------------------------------------------------------------------------
__global__ __launch_bounds__(256) void k3_gemm2(
    const float* __restrict__ spk, const float* __restrict__ W2)
{
    __shared__ float sh[256][33];
    __shared__ float W2t[HID][12];

    const int tid = threadIdx.x;
    for (int i = tid; i < HID * NCLS; i += 256) {
        int j = i / NCLS;
        int o = i - j * NCLS;
        W2t[j][o] = W2[o * HID + j];
    }

    const size_t row0 = (size_t)blockIdx.x * 256;
    float acc[NCLS];
    #pragma unroll
    for (int o = 0; o < NCLS; o++) acc[o] = 0.0f;

    for (int jc = 0; jc < 4; jc++) {
        __syncthreads();
        #pragma unroll
        for (int s4 = 0; s4 < 8; s4++) {
            int f = tid + s4 * 256;
            int r = f >> 3;
            int q = f & 7;
            float4 v = *reinterpret_cast<const float4*>(
                &spk[(row0 + r) * HID + jc * 32 + q * 4]);
            sh[r][q * 4 + 0] = v.x; sh[r][q * 4 + 1] = v.y;
            sh[r][q * 4 + 2] = v.z; sh[r][q * 4 + 3] = v.w;
        }
        __syncthreads();
        #pragma unroll
        for (int j = 0; j < 32; j++) {
            float s = sh[tid][j];
            const float* wr = W2t[jc * 32 + j];
            float4 w0 = *reinterpret_cast<const float4*>(wr);
            float4 w1 = *reinterpret_cast<const float4*>(wr + 4);
            float2 w2 = *reinterpret_cast<const float2*>(wr + 8);
            acc[0] = fmaf(s, w0.x, acc[0]);
            acc[1] = fmaf(s, w0.y, acc[1]);
            acc[2] = fmaf(s, w0.z, acc[2]);
            acc[3] = fmaf(s, w0.w, acc[3]);
            acc[4] = fmaf(s, w1.x, acc[4]);
            acc[5] = fmaf(s, w1.y, acc[5]);
            acc[6] = fmaf(s, w1.z, acc[6]);
            acc[7] = fmaf(s, w1.w, acc[7]);
            acc[8] = fmaf(s, w2.x, acc[8]);
            acc[9] = fmaf(s, w2.y, acc[9]);
        }
    }

    const size_t r = row0 + tid;
    #pragma unroll
    for (int o = 0; o < NCLS; o++)
        g_c2[r * NCLS + o] = acc[o];
}

// ---------------------------------------------------------------------------
__global__ __launch_bounds__(256) void k4_lif2(
    const float* __restrict__ b2, float* __restrict__ outp)
{
    const int id = blockIdx.x * blockDim.x + threadIdx.x;
    const int o = id % NCLS;
    const float bias = __ldg(&b2[o]);

    float mem = 0.0f, acc = 0.0f;
    #pragma unroll
    for (int t = 0; t < TSTEPS; t++) {
        float v = fmaf(mem, DECAYF, g_c2[(size_t)t * (BATCH * NCLS) + id]);
        v = v + bias;
        float s = (v > THRESHF) ? 1.0f : 0.0f;
        acc += s;
        mem = (s != 0.0f) ? 0.0f : v;
    }
    outp[id] = acc;
}

// ---------------------------------------------------------------------------
extern "C" void kernel_launch(void* const* d_in, const int* in_sizes, int n_in,
                              void* d_out, int out_size)
{
    const float* x  = (const float*)d_in[0];
    const float* W1 = (const float*)d_in[1];
    const float* b1 = (const float*)d_in[2];
    const float* W2 = (const float*)d_in[3];
    const float* b2 = (const float*)d_in[4];
    float* out = (float*)d_out;

    float* out_output = out;
    float* out_spk    = out + (size_t)BATCH * NCLS;

    k0_init<<<(HID * INF + 255) / 256, 256>>>(W1);
    k1_hybrid<<<BATCH / 64, 256>>>(x, W1, b1, out_spk);
    k1_fixup<<<256, 128>>>(x, W1, b1, out_spk);
    k3_gemm2<<<(TSTEPS * BATCH) / 256, 256>>>(out_spk, W2);
    k4_lif2<<<(BATCH * NCLS) / 256, 256>>>(b2, out_output);
}

// round 10
// speedup vs baseline: 1.3238x; 1.3238x over previous
#include <cuda_runtime.h>
#include <cuda_bf16.h>

#define BATCH   32768
#define HID     128
#define INF     784
#define NCLS    10
#define TSTEPS  20

#define DECAYF  0.25f
#define THRESHF 1.0f
#define EPSM    2e-4f

#define KCHUNKS (INF / 16)      // 49
#define FIXCAP  (1 << 21)

// CTA split: tensor CTAs cover rows [0, NT*64); fp32 CTAs the rest (exact).
#define NT_CTAS 288
#define NF_CTAS 112
#define FP32_ROW0 (NT_CTAS * 64)    // 18432

// Scratch (device globals)
__device__ float    g_c2[(size_t)TSTEPS * BATCH * NCLS];
__device__ unsigned g_fix_list[FIXCAP];
__device__ unsigned g_fix_cnt;
__device__ __align__(16) unsigned short g_w1a[HID * INF];   // bf16 hi plane
__device__ __align__(16) unsigned short g_w1b[HID * INF];   // bf16 lo plane

// ---------------------------------------------------------------------------
__device__ __forceinline__ void split2(float v, unsigned short& h0, unsigned short& h1)
{
    __nv_bfloat16 b0 = __float2bfloat16_rn(v);
    float r = v - __bfloat162float(b0);
    __nv_bfloat16 b1 = __float2bfloat16_rn(r);
    h0 = __bfloat16_as_ushort(b0);
    h1 = __bfloat16_as_ushort(b1);
}

__device__ __forceinline__ void mma_bf16(float* d, const unsigned* a, const unsigned* b)
{
    asm volatile(
        "mma.sync.aligned.m16n8k16.row.col.f32.bf16.bf16.f32 "
        "{%0,%1,%2,%3}, {%4,%5,%6,%7}, {%8,%9}, {%0,%1,%2,%3};"
        : "+f"(d[0]), "+f"(d[1]), "+f"(d[2]), "+f"(d[3])
        : "r"(a[0]), "r"(a[1]), "r"(a[2]), "r"(a[3]), "r"(b[0]), "r"(b[1]));
}

__global__ void k0_init(const float* __restrict__ W1)
{
    if (blockIdx.x == 0 && threadIdx.x == 0) g_fix_cnt = 0;
    int i = blockIdx.x * blockDim.x + threadIdx.x;
    if (i < HID * INF) {
        unsigned short h0, h1;
        split2(W1[i], h0, h1);
        g_w1a[i] = h0;
        g_w1b[i] = h1;
    }
}

// ---------------------------------------------------------------------------
// K1 hybrid (CTA-level split):
//   blockIdx.x <  NT_CTAS: R5 tensor body, 64 rows/CTA, margin-fixup.
//   blockIdx.x >= NT_CTAS: R1 exact fp32 body, 128 rows/CTA, no fixup.
// One 36KB smem arena aliased by both branches.
// ---------------------------------------------------------------------------
#define ASTRIDE 24

__global__ __launch_bounds__(256) void k1_hybrid(
    const float* __restrict__ x, const float* __restrict__ W1,
    const float* __restrict__ b1, float* __restrict__ out_spk)
{
    __shared__ __align__(16) char SMEMU[36864];
    const int tid = threadIdx.x;

    if (blockIdx.x < NT_CTAS) {
        // ================== TENSOR PATH (R5 verbatim) ==================
        const int lane = tid & 31;
        const int wid  = tid >> 5;
        const int g    = lane >> 2;
        const int tg   = lane & 3;
        const int wm   = wid >> 2;
        const int wn   = wid & 3;
        const int m0   = blockIdx.x * 64;

        const int sm_r = tid >> 2;
        const int skq  = (tid & 3) * 4;
        const int bn   = tid >> 1;
        const int bkh  = (tid & 1) * 8;

        unsigned short* As = (unsigned short*)SMEMU;              // [2][2][64*24]
        unsigned short* Bs = (unsigned short*)(SMEMU + 12288);    // [2][2][128*24]

        float acc[2][4][4];
        #pragma unroll
        for (int mt = 0; mt < 2; mt++)
            #pragma unroll
            for (int nt = 0; nt < 4; nt++)
                #pragma unroll
                for (int r = 0; r < 4; r++) acc[mt][nt][r] = 0.0f;

        // prologue: stage chunk 0 into buf 0
        {
            float4 ax = *reinterpret_cast<const float4*>(&x[(size_t)(m0 + sm_r) * INF + skq]);
            float av[4] = {ax.x, ax.y, ax.z, ax.w};
            unsigned short p0[4], p1[4];
            #pragma unroll
            for (int i = 0; i < 4; i++) split2(av[i], p0[i], p1[i]);
            *reinterpret_cast<uint2*>(&As[0 * (64 * ASTRIDE) + sm_r * ASTRIDE + skq]) = *reinterpret_cast<uint2*>(p0);
            *reinterpret_cast<uint2*>(&As[1 * (64 * ASTRIDE) + sm_r * ASTRIDE + skq]) = *reinterpret_cast<uint2*>(p1);

            uint4 va = *reinterpret_cast<const uint4*>(&g_w1a[bn * INF + bkh]);
            uint4 vb = *reinterpret_cast<const uint4*>(&g_w1b[bn * INF + bkh]);
            *reinterpret_cast<uint4*>(&Bs[0 * (128 * ASTRIDE) + bn * ASTRIDE + bkh]) = va;
            *reinterpret_cast<uint4*>(&Bs[1 * (128 * ASTRIDE) + bn * ASTRIDE + bkh]) = vb;
        }
        __syncthreads();

        int buf = 0;
        for (int kc = 0; kc < KCHUNKS; kc++) {
            float4 pax;
            uint4 pba, pbb;
            if (kc < KCHUNKS - 1) {
                int k0 = (kc + 1) * 16;
                pax = *reinterpret_cast<const float4*>(&x[(size_t)(m0 + sm_r) * INF + k0 + skq]);
                pba = *reinterpret_cast<const uint4*>(&g_w1a[bn * INF + k0 + bkh]);
                pbb = *reinterpret_cast<const uint4*>(&g_w1b[bn * INF + k0 + bkh]);
            }

            unsigned aF[2][2][4];
            #pragma unroll
            for (int s = 0; s < 2; s++)
                #pragma unroll
                for (int mt = 0; mt < 2; mt++) {
                    const unsigned short* ap = &As[(buf * 2 + s) * (64 * ASTRIDE) + (wm * 32 + mt * 16) * ASTRIDE];
                    aF[s][mt][0] = *reinterpret_cast<const unsigned*>(&ap[(g)     * ASTRIDE + tg * 2]);
                    aF[s][mt][1] = *reinterpret_cast<const unsigned*>(&ap[(g + 8) * ASTRIDE + tg * 2]);
                    aF[s][mt][2] = *reinterpret_cast<const unsigned*>(&ap[(g)     * ASTRIDE + tg * 2 + 8]);
                    aF[s][mt][3] = *reinterpret_cast<const unsigned*>(&ap[(g + 8) * ASTRIDE + tg * 2 + 8]);
                }
            unsigned bF[2][4][2];
            #pragma unroll
            for (int s = 0; s < 2; s++)
                #pragma unroll
                for (int nt = 0; nt < 4; nt++) {
                    const unsigned short* bp = &Bs[(buf * 2 + s) * (128 * ASTRIDE) + (wn * 32 + nt * 8 + g) * ASTRIDE];
                    bF[s][nt][0] = *reinterpret_cast<const unsigned*>(&bp[tg * 2]);
                    bF[s][nt][1] = *reinterpret_cast<const unsigned*>(&bp[tg * 2 + 8]);
                }

            #pragma unroll
            for (int p = 0; p < 3; p++) {
                const int PI[3] = {0, 0, 1};
                const int PJ[3] = {0, 1, 0};
                int i = PI[p], j = PJ[p];
                #pragma unroll
                for (int mt = 0; mt < 2; mt++)
                    #pragma unroll
                    for (int nt = 0; nt < 4; nt++)
                        mma_bf16(acc[mt][nt], aF[i][mt], bF[j][nt]);
            }

            if (kc < KCHUNKS - 1) {
                int ob = buf ^ 1;
                float av[4] = {pax.x, pax.y, pax.z, pax.w};
                unsigned short p0[4], p1[4];
                #pragma unroll
                for (int i = 0; i < 4; i++) split2(av[i], p0[i], p1[i]);
                *reinterpret_cast<uint2*>(&As[(ob * 2 + 0) * (64 * ASTRIDE) + sm_r * ASTRIDE + skq]) = *reinterpret_cast<uint2*>(p0);
                *reinterpret_cast<uint2*>(&As[(ob * 2 + 1) * (64 * ASTRIDE) + sm_r * ASTRIDE + skq]) = *reinterpret_cast<uint2*>(p1);
                *reinterpret_cast<uint4*>(&Bs[(ob * 2 + 0) * (128 * ASTRIDE) + bn * ASTRIDE + bkh]) = pba;
                *reinterpret_cast<uint4*>(&Bs[(ob * 2 + 1) * (128 * ASTRIDE) + bn * ASTRIDE + bkh]) = pbb;
            }
            __syncthreads();
            buf ^= 1;
        }

        // epilogue: + b1, LIF with margin tracking, write spikes
        float cur[2][4][4];
        #pragma unroll
        for (int nt = 0; nt < 4; nt++) {
            float2 bv = *reinterpret_cast<const float2*>(&b1[wn * 32 + nt * 8 + tg * 2]);
            #pragma unroll
            for (int mt = 0; mt < 2; mt++) {
                cur[mt][nt][0] = acc[mt][nt][0] + bv.x;
                cur[mt][nt][1] = acc[mt][nt][1] + bv.y;
                cur[mt][nt][2] = acc[mt][nt][2] + bv.x;
                cur[mt][nt][3] = acc[mt][nt][3] + bv.y;
            }
        }

        float mem[2][4][4];
        unsigned badm[2][4];
        #pragma unroll
        for (int mt = 0; mt < 2; mt++)
            #pragma unroll
            for (int nt = 0; nt < 4; nt++) {
                badm[mt][nt] = 0u;
                #pragma unroll
                for (int r = 0; r < 4; r++) mem[mt][nt][r] = 0.0f;
            }

        for (int t = 0; t < TSTEPS; t++) {
            float* pt = out_spk + (size_t)t * ((size_t)BATCH * HID);
            #pragma unroll
            for (int mt = 0; mt < 2; mt++) {
                int r0 = m0 + wm * 32 + mt * 16 + g;
                #pragma unroll
                for (int nt = 0; nt < 4; nt++) {
                    int n = wn * 32 + nt * 8 + tg * 2;
                    float s[4];
                    #pragma unroll
                    for (int r = 0; r < 4; r++) {
                        float m = fmaf(mem[mt][nt][r], DECAYF, cur[mt][nt][r]);
                        if (fabsf(m - THRESHF) < EPSM) badm[mt][nt] |= (1u << r);
                        s[r] = (m > THRESHF) ? 1.0f : 0.0f;
                        mem[mt][nt][r] = (s[r] != 0.0f) ? 0.0f : m;
                    }
                    float2 v0 = {s[0], s[1]};
                    float2 v1 = {s[2], s[3]};
                    *reinterpret_cast<float2*>(&pt[(size_t)r0 * HID + n])       = v0;
                    *reinterpret_cast<float2*>(&pt[(size_t)(r0 + 8) * HID + n]) = v1;
                }
            }
        }

        #pragma unroll
        for (int mt = 0; mt < 2; mt++)
            #pragma unroll
            for (int nt = 0; nt < 4; nt++)
                if (badm[mt][nt]) {
                    #pragma unroll
                    for (int r = 0; r < 4; r++)
                        if (badm[mt][nt] & (1u << r)) {
                            int row = m0 + wm * 32 + mt * 16 + g + ((r >> 1) ? 8 : 0);
                            int col = wn * 32 + nt * 8 + tg * 2 + (r & 1);
                            unsigned pos = atomicAdd(&g_fix_cnt, 1u);
                            if (pos < FIXCAP)
                                g_fix_list[pos] = (unsigned)(row * HID + col);
                        }
                }
    } else {
        // ================== FP32 PATH (R1 verbatim mainloop, exact) ==================
        float* FA = (float*)SMEMU;            // [16][128]  (k-major, m cols)
        float* FB = (float*)(SMEMU + 8192);   // [16][128]  (k-major, n cols)

        const int ftx = tid & 15;            // n group
        const int fty = tid >> 4;            // m group
        const int m0  = FP32_ROW0 + (blockIdx.x - NT_CTAS) * 128;

        float acc[8][8];
        #pragma unroll
        for (int i = 0; i < 8; i++)
            #pragma unroll
            for (int j = 0; j < 8; j++) acc[i][j] = 0.0f;

        for (int k0 = 0; k0 < INF; k0 += 16) {
            __syncthreads();
            #pragma unroll
            for (int it = 0; it < 2; it++) {
                int f  = tid + it * 256;
                int m  = f >> 2;
                int kq = (f & 3) * 4;
                float4 v = *reinterpret_cast<const float4*>(&x[(size_t)(m0 + m) * INF + k0 + kq]);
                FA[(kq + 0) * 128 + m] = v.x; FA[(kq + 1) * 128 + m] = v.y;
                FA[(kq + 2) * 128 + m] = v.z; FA[(kq + 3) * 128 + m] = v.w;
            }
            #pragma unroll
            for (int it = 0; it < 2; it++) {
                int f  = tid + it * 256;
                int n  = f >> 2;
                int kq = (f & 3) * 4;
                float4 v = *reinterpret_cast<const float4*>(&W1[(size_t)n * INF + k0 + kq]);
                FB[(kq + 0) * 128 + n] = v.x; FB[(kq + 1) * 128 + n] = v.y;
                FB[(kq + 2) * 128 + n] = v.z; FB[(kq + 3) * 128 + n] = v.w;
            }
            __syncthreads();

            #pragma unroll
            for (int k = 0; k < 16; k++) {
                float4 a0 = *reinterpret_cast<const float4*>(&FA[k * 128 + fty * 8]);
                float4 a1 = *reinterpret_cast<const float4*>(&FA[k * 128 + fty * 8 + 4]);
                float4 b0 = *reinterpret_cast<const float4*>(&FB[k * 128 + ftx * 8]);
                float4 b1v = *reinterpret_cast<const float4*>(&FB[k * 128 + ftx * 8 + 4]);
                float a[8] = {a0.x, a0.y, a0.z, a0.w, a1.x, a1.y, a1.z, a1.w};
                float b[8] = {b0.x, b0.y, b0.z, b0.w, b1v.x, b1v.y, b1v.z, b1v.w};
                #pragma unroll
                for (int i = 0; i < 8; i++)
                    #pragma unroll
                    for (int j = 0; j < 8; j++)
                        acc[i][j] = fmaf(a[i], b[j], acc[i][j]);
            }
        }

        // epilogue: per 8-row strip: cur = acc + b1, 20-step LIF, stores.
        float bb[8];
        #pragma unroll
        for (int j = 0; j < 8; j++) bb[j] = __ldg(&b1[ftx * 8 + j]);

        #pragma unroll
        for (int i = 0; i < 8; i++) {
            float cur[8], mem[8];
            #pragma unroll
            for (int j = 0; j < 8; j++) {
                cur[j] = acc[i][j] + bb[j];
                mem[j] = 0.0f;
            }
            const size_t rowoff = (size_t)(m0 + fty * 8 + i) * HID + ftx * 8;
            for (int t = 0; t < TSTEPS; t++) {
                float s[8];
                #pragma unroll
                for (int j = 0; j < 8; j++) {
                    mem[j] = fmaf(mem[j], DECAYF, cur[j]);
                    s[j] = (mem[j] > THRESHF) ? 1.0f : 0.0f;
                    mem[j] = (s[j] != 0.0f) ? 0.0f : mem[j];
                }
                float4 v0 = {s[0], s[1], s[2], s[3]};
                float4 v1 = {s[4], s[5], s[6], s[7]};
                float* pr = out_spk + (size_t)t * ((size_t)BATCH * HID) + rowoff;
                *reinterpret_cast<float4*>(pr)     = v0;
                *reinterpret_cast<float4*>(pr + 4) = v1;
            }
        }
    }
}

// ---------------------------------------------------------------------------
// K1b fixup: exact sequential-k fp32 recompute of spikes (bitwise R1 recipe).
// ---------------------------------------------------------------------------
__global__ __launch_bounds__(128) void k1_fixup(
    const float* __restrict__ x, const float* __restrict__ W1,
    const float* __restrict__ b1, float* __restrict__ out_spk)
{
    const unsigned cnt = min(*(volatile unsigned*)&g_fix_cnt, (unsigned)FIXCAP);
    const int stride = gridDim.x * blockDim.x;

    for (unsigned i = blockIdx.x * blockDim.x + threadIdx.x; i < cnt; i += stride) {
        unsigned idx = g_fix_list[i];
        int b = idx >> 7;
        int j = idx & (HID - 1);

        const float* xr = x  + (size_t)b * INF;
        const float* wr = W1 + (size_t)j * INF;
        float a = 0.0f;
        for (int k = 0; k < INF; k++)
            a = fmaf(__ldg(&xr[k]), __ldg(&wr[k]), a);
        float curv = a + __ldg(&b1[j]);

        float m = 0.0f;
        for (int t = 0; t < TSTEPS; t++) {
            m = fmaf(m, DECAYF, curv);
            float s = (m > THRESHF) ? 1.0f : 0.0f;
            out_spk[(size_t)t * ((size_t)BATCH * HID) + idx] = s;
            m = (s != 0.0f) ? 0.0f : m;
        }
    }
}

// ---------------------------------------------------------------------------
// K3: c2 = spk @ W2^T (verbatim R5 — proven, bitwise == R1 chain).
// ---------------------------------------------------------------------------
__global__ __launch_bounds__(256) void k3_gemm2(
    const float* __restrict__ spk, const float* __restrict__ W2)
{
    __shared__ float sh[256][33];
    __shared__ float W2t[HID][12];

    const int tid = threadIdx.x;
    for (int i = tid; i < HID * NCLS; i += 256) {
        int j = i / NCLS;
        int o = i - j * NCLS;
        W2t[j][o] = W2[o * HID + j];
    }

    const size_t row0 = (size_t)blockIdx.x * 256;
    float acc[NCLS];
    #pragma unroll
    for (int o = 0; o < NCLS; o++) acc[o] = 0.0f;

    for (int jc = 0; jc < 4; jc++) {
        __syncthreads();
        #pragma unroll
        for (int s4 = 0; s4 < 8; s4++) {
            int f = tid + s4 * 256;
            int r = f >> 3;
            int q = f & 7;
            float4 v = *reinterpret_cast<const float4*>(
                &spk[(row0 + r) * HID + jc * 32 + q * 4]);
            sh[r][q * 4 + 0] = v.x; sh[r][q * 4 + 1] = v.y;
            sh[r][q * 4 + 2] = v.z; sh[r][q * 4 + 3] = v.w;
        }
        __syncthreads();
        #pragma unroll
        for (int j = 0; j < 32; j++) {
            float s = sh[tid][j];
            const float* wr = W2t[jc * 32 + j];
            float4 w0 = *reinterpret_cast<const float4*>(wr);
            float4 w1 = *reinterpret_cast<const float4*>(wr + 4);
            float2 w2 = *reinterpret_cast<const float2*>(wr + 8);
            acc[0] = fmaf(s, w0.x, acc[0]);
            acc[1] = fmaf(s, w0.y, acc[1]);
            acc[2] = fmaf(s, w0.z, acc[2]);
            acc[3] = fmaf(s, w0.w, acc[3]);
            acc[4] = fmaf(s, w1.x, acc[4]);
            acc[5] = fmaf(s, w1.y, acc[5]);
            acc[6] = fmaf(s, w1.z, acc[6]);
            acc[7] = fmaf(s, w1.w, acc[7]);
            acc[8] = fmaf(s, w2.x, acc[8]);
            acc[9] = fmaf(s, w2.y, acc[9]);
        }
    }

    const size_t r = row0 + tid;
    #pragma unroll
    for (int o = 0; o < NCLS; o++)
        g_c2[r * NCLS + o] = acc[o];
}

// ---------------------------------------------------------------------------
__global__ __launch_bounds__(256) void k4_lif2(
    const float* __restrict__ b2, float* __restrict__ outp)
{
    const int id = blockIdx.x * blockDim.x + threadIdx.x;
    const int o = id % NCLS;
    const float bias = __ldg(&b2[o]);

    float mem = 0.0f, acc = 0.0f;
    #pragma unroll
    for (int t = 0; t < TSTEPS; t++) {
        float v = fmaf(mem, DECAYF, g_c2[(size_t)t * (BATCH * NCLS) + id]);
        v = v + bias;
        float s = (v > THRESHF) ? 1.0f : 0.0f;
        acc += s;
        mem = (s != 0.0f) ? 0.0f : v;
    }
    outp[id] = acc;
}

// ---------------------------------------------------------------------------
extern "C" void kernel_launch(void* const* d_in, const int* in_sizes, int n_in,
                              void* d_out, int out_size)
{
    const float* x  = (const float*)d_in[0];
    const float* W1 = (const float*)d_in[1];
    const float* b1 = (const float*)d_in[2];
    const float* W2 = (const float*)d_in[3];
    const float* b2 = (const float*)d_in[4];
    float* out = (float*)d_out;

    float* out_output = out;
    float* out_spk    = out + (size_t)BATCH * NCLS;

    k0_init<<<(HID * INF + 255) / 256, 256>>>(W1);
    k1_hybrid<<<NT_CTAS + NF_CTAS, 256>>>(x, W1, b1, out_spk);
    k1_fixup<<<256, 128>>>(x, W1, b1, out_spk);
    k3_gemm2<<<(TSTEPS * BATCH) / 256, 256>>>(out_spk, W2);
    k4_lif2<<<(BATCH * NCLS) / 256, 256>>>(b2, out_output);
}